// round 15
// baseline (speedup 1.0000x reference)
#include <cuda_runtime.h>
#include <cuda_fp16.h>
#include <stdint.h>

// Problem constants
#define BATCH 16384
#define HID   512
#define ALPH  64
#define SEQL  256
#define BOSID 64
#define G4    2048            // 4*HID
#define NTILE 16              // G4/128
#define MTILE 128             // BATCH/128
#define PLANE 18432           // 128 rows x 144B (64 fp16 + 16B pad)
#define BUFSZ (6 * PLANE)     // 110592: one 6-plane chunk buffer
#define DSM_BYTES (2 * BUFSZ) // 221184: double-buffered
#define INV2048 (1.0f/2048.0f)
#define NTHREADS 512

// ---------------- device scratch (static, allowed) ----------------
__device__ float d_h[BATCH * HID];
__device__ float d_c[BATCH * HID];
__device__ float d_gates[BATCH * G4];     // full gate partial (acc1 + acc2/2048)
__device__ float d_E[(ALPH + 1) * G4];
__device__ float d_logits[BATCH * ALPH];
__device__ int   d_tok[BATCH];
__device__ unsigned d_keys[SEQL * 2];
// exact 3-limb fp16 decomposition (each limb renormalized): x = l0 + (l1+l2)/2048
__device__ __half d_h0[BATCH * HID], d_h1[BATCH * HID], d_h2[BATCH * HID];
__device__ __half d_W0[G4 * HID],   d_W1[G4 * HID],   d_W2[G4 * HID];
__device__ unsigned g_bar = 0;
__device__ unsigned g_gen = 0;

// ---------------- helpers ----------------
__device__ __forceinline__ uint32_t smem_to_u32(const void* p) {
    uint32_t a;
    asm("{ .reg .u64 t; cvta.to.shared.u64 t, %1; cvt.u32.u64 %0, t; }" : "=r"(a) : "l"(p));
    return a;
}

#define LDSM4(r0, r1, r2, r3, addr) \
    asm volatile("ldmatrix.sync.aligned.m8n8.x4.shared.b16 {%0,%1,%2,%3}, [%4];" \
        : "=r"(r0), "=r"(r1), "=r"(r2), "=r"(r3) : "r"(addr))

#define MMA16816(d, a, b0, b1) \
    asm volatile("mma.sync.aligned.m16n8k16.row.col.f32.f16.f16.f32 " \
        "{%0,%1,%2,%3}, {%4,%5,%6,%7}, {%8,%9}, {%0,%1,%2,%3};" \
        : "+f"((d)[0]), "+f"((d)[1]), "+f"((d)[2]), "+f"((d)[3]) \
        : "r"((a)[0]), "r"((a)[1]), "r"((a)[2]), "r"((a)[3]), "r"(b0), "r"(b1))

#define CP_ASYNC16(saddr, gaddr) \
    asm volatile("cp.async.cg.shared.global [%0], [%1], 16;" :: "r"(saddr), "l"(gaddr) : "memory")
#define CP_COMMIT() asm volatile("cp.async.commit_group;" ::: "memory")
#define CP_WAIT1()  asm volatile("cp.async.wait_group 1;" ::: "memory")
#define CP_WAIT0()  asm volatile("cp.async.wait_group 0;" ::: "memory")

// multiply a packed half2 fragment reg by 2^-11 (exact scale)
__device__ __forceinline__ uint32_t hdescale(uint32_t v) {
    __half2 x = *reinterpret_cast<__half2*>(&v);
    x = __hmul2(x, __half2half2(__float2half(4.8828125e-4f)));
    return *reinterpret_cast<uint32_t*>(&x);
}

// exact 3-limb split: x = l0 + l1/2048 + l2/2048
__device__ __forceinline__ void split3(float x, __half& l0, __half& l1, __half& l2) {
    l0 = __float2half_rn(x);
    float r1 = x - __half2float(l0);
    l1 = __float2half_rn(r1 * 2048.f);
    float r2 = r1 - __half2float(l1) * INV2048;
    l2 = __float2half_rn(r2 * 2048.f);
}

// ---------------- grid-wide barrier (all CTAs co-resident) ----------------
__device__ __forceinline__ void gsync() {
    __threadfence();
    __syncthreads();
    if (threadIdx.x == 0) {
        unsigned nb = gridDim.x;
        unsigned gen = *(volatile unsigned*)&g_gen;
        if (atomicAdd(&g_bar, 1u) == nb - 1u) {
            atomicExch(&g_bar, 0u);
            __threadfence();
            atomicAdd(&g_gen, 1u);
        } else {
            while (*(volatile unsigned*)&g_gen == gen) __nanosleep(64);
        }
        __threadfence();
    }
    __syncthreads();
}

// ---------------- threefry2x32 (bit-exact JAX, counter mode) ----------------
__device__ __forceinline__ unsigned rotl32(unsigned v, int r) {
    return (v << r) | (v >> (32 - r));
}
__device__ __forceinline__ void tf_round(unsigned &x0, unsigned &x1, int r) {
    x0 += x1; x1 = rotl32(x1, r); x1 ^= x0;
}
__device__ __forceinline__ uint2 threefry2x32(unsigned k0, unsigned k1,
                                              unsigned x0, unsigned x1) {
    unsigned ks2 = k0 ^ k1 ^ 0x1BD11BDAu;
    x0 += k0; x1 += k1;
    tf_round(x0, x1, 13); tf_round(x0, x1, 15); tf_round(x0, x1, 26); tf_round(x0, x1, 6);
    x0 += k1; x1 += ks2 + 1u;
    tf_round(x0, x1, 17); tf_round(x0, x1, 29); tf_round(x0, x1, 16); tf_round(x0, x1, 24);
    x0 += ks2; x1 += k0 + 2u;
    tf_round(x0, x1, 13); tf_round(x0, x1, 15); tf_round(x0, x1, 26); tf_round(x0, x1, 6);
    x0 += k0; x1 += k1 + 3u;
    tf_round(x0, x1, 17); tf_round(x0, x1, 29); tf_round(x0, x1, 16); tf_round(x0, x1, 24);
    x0 += k1; x1 += ks2 + 4u;
    tf_round(x0, x1, 13); tf_round(x0, x1, 15); tf_round(x0, x1, 26); tf_round(x0, x1, 6);
    x0 += ks2; x1 += k0 + 5u;
    return make_uint2(x0, x1);
}
__device__ __forceinline__ float sigmoidf_(float x) { return 1.f / (1.f + expf(-x)); }
__device__ __forceinline__ float gumbel_from_bits(unsigned bits) {
    float u = __uint_as_float((bits >> 9) | 0x3f800000u) - 1.0f;
    u = fmaxf(1.17549435e-38f, u + 1.17549435e-38f);
    return -logf(-logf(u));
}
__device__ __forceinline__ unsigned pbits32(unsigned k0, unsigned k1, unsigned f) {
    uint2 y = threefry2x32(k0, k1, 0u, f);
    return y.x ^ y.y;
}

// ---------------- chunk prefetch via cp.async (6 planes, 64-K slice) --------
__device__ __forceinline__ void prefetch_chunk(int kb, int m0, int n0, uint32_t sbase) {
    const int tid = threadIdx.x;
#pragma unroll
    for (int p = 0; p < 6; p++) {
        const __half* s = (p == 0) ? d_h0 : (p == 1) ? d_h1 : (p == 2) ? d_h2
                        : (p == 3) ? d_W0 : (p == 4) ? d_W1 : d_W2;
        const size_t rb = (p < 3) ? (size_t)m0 : (size_t)n0;
#pragma unroll
        for (int qq = 0; qq < 2; qq++) {
            int q = tid + qq * NTHREADS;     // 0..1023
            int r = q >> 3, sg = q & 7;
            const void* g = (const void*)&s[(rb + r) * HID + kb + sg * 8];
            uint32_t sa = sbase + p * PLANE + (uint32_t)(r * 144 + sg * 16);
            CP_ASYNC16(sa, g);
        }
    }
}

// ---------------- flat-pipelined HMMA GEMM phase (bit-identical numerics) ---
// One continuous double-buffered (tile,chunk) stream per CTA. MMA order per
// tile/chunk/kk identical to R14.
__device__ void gemm_phase(uint32_t dsm_u32) {
    const int tid = threadIdx.x;
    const int wid = tid >> 5;
    const int lane = tid & 31;
    const int mwarp = wid >> 2;      // 0..3
    const int nwarp = wid & 3;       // 0..3

    const int ntl = (MTILE * NTILE - 1 - (int)blockIdx.x) / (int)gridDim.x + 1;
    const int total = ntl * 8;

    float acc1[2][4][4], acc2[2][4][4];

    const int a_r = (lane & 15);
    const int a_c2 = ((lane >> 4) << 3) * 2;
    const int b_r = ((lane >> 4) << 3) + (lane & 7);
    const int b_c2 = (((lane >> 3) & 1) << 3) * 2;

    // prologue: prefetch (tile0, chunk0)
    {
        const int t0 = blockIdx.x;
        prefetch_chunk(0, (t0 / NTILE) * 128, (t0 & (NTILE - 1)) * 128, dsm_u32);
        CP_COMMIT();
    }

    for (int i = 0; i < total; i++) {
        const int j = i >> 3, c = i & 7;
        const int tile = blockIdx.x + j * (int)gridDim.x;
        const int n0 = (tile & (NTILE - 1)) * 128;
        const int m0 = (tile / NTILE) * 128;

        if (c == 0) {
#pragma unroll
            for (int mi = 0; mi < 2; mi++)
#pragma unroll
                for (int ni = 0; ni < 4; ni++)
#pragma unroll
                    for (int e = 0; e < 4; e++) { acc1[mi][ni][e] = 0.f; acc2[mi][ni][e] = 0.f; }
        }

        if (i + 1 < total) {
            const int i2 = i + 1;
            const int j2 = i2 >> 3, c2 = i2 & 7;
            const int tl2 = blockIdx.x + j2 * (int)gridDim.x;
            prefetch_chunk(c2 * 64, (tl2 / NTILE) * 128, (tl2 & (NTILE - 1)) * 128,
                           dsm_u32 + (uint32_t)(i2 & 1) * BUFSZ);
            CP_COMMIT();
            CP_WAIT1();
        } else {
            CP_WAIT0();
        }
        __syncthreads();

        const uint32_t bufr = dsm_u32 + (uint32_t)(i & 1) * BUFSZ;
#pragma unroll
        for (int kk = 0; kk < 4; kk++) {
            const int kB = kk * 32;
            uint32_t a0[2][4], a1[2][4], a1d[2][4], a2[2][4];
#pragma unroll
            for (int mi = 0; mi < 2; mi++) {
                uint32_t off = (uint32_t)(mwarp * 32 + mi * 16 + a_r) * 144 + kB + a_c2;
                LDSM4(a0[mi][0], a0[mi][1], a0[mi][2], a0[mi][3], bufr + off);
                LDSM4(a1[mi][0], a1[mi][1], a1[mi][2], a1[mi][3], bufr + PLANE + off);
                LDSM4(a2[mi][0], a2[mi][1], a2[mi][2], a2[mi][3], bufr + 2 * PLANE + off);
#pragma unroll
                for (int jq = 0; jq < 4; jq++) a1d[mi][jq] = hdescale(a1[mi][jq]);
            }
#pragma unroll
            for (int grp = 0; grp < 2; grp++) {
                uint32_t off = (uint32_t)(nwarp * 32 + grp * 16 + b_r) * 144 + kB + b_c2;
                uint32_t b0[4], b1[4], b2[4];
                LDSM4(b0[0], b0[1], b0[2], b0[3], bufr + 3 * PLANE + off);
                LDSM4(b1[0], b1[1], b1[2], b1[3], bufr + 4 * PLANE + off);
                LDSM4(b2[0], b2[1], b2[2], b2[3], bufr + 5 * PLANE + off);
                const int ni0 = 2 * grp, ni1 = ni0 + 1;
#pragma unroll
                for (int mi = 0; mi < 2; mi++) {
                    MMA16816(acc1[mi][ni0], a0[mi], b0[0], b0[1]);   // l0*g0
                    MMA16816(acc1[mi][ni1], a0[mi], b0[2], b0[3]);
                    MMA16816(acc2[mi][ni0], a0[mi], b1[0], b1[1]);   // l0*g1
                    MMA16816(acc2[mi][ni1], a0[mi], b1[2], b1[3]);
                    MMA16816(acc2[mi][ni0], a1[mi], b0[0], b0[1]);   // l1*g0
                    MMA16816(acc2[mi][ni1], a1[mi], b0[2], b0[3]);
                    MMA16816(acc2[mi][ni0], a0[mi], b2[0], b2[1]);   // l0*g2
                    MMA16816(acc2[mi][ni1], a0[mi], b2[2], b2[3]);
                    MMA16816(acc2[mi][ni0], a2[mi], b0[0], b0[1]);   // l2*g0
                    MMA16816(acc2[mi][ni1], a2[mi], b0[2], b0[3]);
                    MMA16816(acc2[mi][ni0], a1d[mi], b1[0], b1[1]);  // (l1*2^-11)*g1
                    MMA16816(acc2[mi][ni1], a1d[mi], b1[2], b1[3]);
                }
            }
        }
        __syncthreads();   // buffer(i) free before prefetch(i+2) overwrites

        if (c == 7) {
            // epilogue (overlaps next tile's in-flight prefetch)
            const int g = lane >> 2, t4 = lane & 3;
#pragma unroll
            for (int mi = 0; mi < 2; mi++) {
                const int row = m0 + mwarp * 32 + mi * 16 + g;
#pragma unroll
                for (int ni = 0; ni < 4; ni++) {
                    const int col = n0 + nwarp * 32 + ni * 8 + 2 * t4;
                    float* Cp = d_gates + (size_t)row * G4 + col;
                    Cp[0] = acc1[mi][ni][0] + acc2[mi][ni][0] * INV2048;
                    Cp[1] = acc1[mi][ni][1] + acc2[mi][ni][1] * INV2048;
                    float* Cp2 = Cp + (size_t)8 * G4;
                    Cp2[0] = acc1[mi][ni][2] + acc2[mi][ni][2] * INV2048;
                    Cp2[1] = acc1[mi][ni][3] + acc2[mi][ni][3] * INV2048;
                }
            }
        }
    }
}

// ---------------- sample for a 64-row chunk (256-thread half) ---------------
__device__ void sample_chunk(int ch, int t, float* __restrict__ out, int htid) {
    const int b0 = ch * 64;
    const int hwid = htid >> 5;
    const int lane = htid & 31;
    const unsigned k0 = __ldcg(&d_keys[2 * t]);
    const unsigned k1 = __ldcg(&d_keys[2 * t + 1]);

    for (int rr = 0; rr < 8; rr++) {
        const int lb = hwid * 8 + rr;
        const int b = b0 + lb;

        const int a0 = lane, a1 = lane + 32;
        const unsigned f0 = (unsigned)b * ALPH + a0;
        const unsigned f1 = f0 + 32u;
        unsigned bits0 = pbits32(k0, k1, f0);
        unsigned bits1 = pbits32(k0, k1, f1);

        float l0 = d_logits[(size_t)b * ALPH + a0];
        float l1 = d_logits[(size_t)b * ALPH + a1];
        float z0 = l0 + gumbel_from_bits(bits0);
        float z1 = l1 + gumbel_from_bits(bits1);

        float v; int idx;
        if (z1 > z0) { v = z1; idx = a1; } else { v = z0; idx = a0; }
#pragma unroll
        for (int off = 16; off > 0; off >>= 1) {
            float vo = __shfl_down_sync(0xffffffffu, v, off);
            int io = __shfl_down_sync(0xffffffffu, idx, off);
            if (vo > v || (vo == v && io < idx)) { v = vo; idx = io; }
        }
        idx = __shfl_sync(0xffffffffu, idx, 0);

        float m = fmaxf(l0, l1);
#pragma unroll
        for (int off = 16; off > 0; off >>= 1)
            m = fmaxf(m, __shfl_xor_sync(0xffffffffu, m, off));
        float s = expf(l0 - m) + expf(l1 - m);
#pragma unroll
        for (int off = 16; off > 0; off >>= 1)
            s += __shfl_xor_sync(0xffffffffu, s, off);

        float ltok = __shfl_sync(0xffffffffu, (idx < 32 ? l0 : l1), idx & 31);

        if (lane == 0) {
            d_tok[b] = idx;
            out[(size_t)b * SEQL + t] = (float)idx;
            out[(size_t)BATCH * SEQL + b] += ltok - m - logf(s);
        }
    }
}

// ---------------- cell + head for a 64-row chunk (256-thread half) ----------
__device__ void cell_head(int ch, int use_tok, int has_gates, int czero,
                          char* pchar,
                          const float* __restrict__ hw, const float* __restrict__ hb,
                          int htid) {
    const int b0 = ch * 64;

    for (int e = htid; e < 64 * HID; e += 256) {
        int lr = e >> 9, k = e & (HID - 1);
        int b = b0 + lr;
        int tk = use_tok ? d_tok[b] : BOSID;
        const float* Er = d_E + (size_t)tk * G4;
        float gi = __ldcg(&Er[k]);
        float gf = __ldcg(&Er[HID + k]);
        float gg = __ldcg(&Er[2 * HID + k]);
        float go = __ldcg(&Er[3 * HID + k]);
        if (has_gates) {
            const float* g1 = d_gates + (size_t)b * G4;
            gi += __ldcg(&g1[k]);
            gf += __ldcg(&g1[HID + k]);
            gg += __ldcg(&g1[2 * HID + k]);
            go += __ldcg(&g1[3 * HID + k]);
        }
        size_t i = (size_t)b * HID + k;
        float cc = czero ? 0.f : d_c[i];
        float c2 = sigmoidf_(gf) * cc + sigmoidf_(gi) * tanhf(gg);
        d_c[i] = c2;
        float h2 = sigmoidf_(go) * tanhf(c2);
        d_h[i] = h2;
        __half q0, q1, q2;
        split3(h2, q0, q1, q2);
        d_h0[i] = q0; d_h1[i] = q1; d_h2[i] = q2;
    }
    __syncthreads();

    // head: logits[64x64] = h @ head_w^T + head_b
    float (*shh)[65] = (float (*)[65])pchar;
    float (*shw)[65] = (float (*)[65])(pchar + 64 * 65 * 4);
    const int ty = htid >> 4, tx = htid & 15;
    float acc[4][4];
#pragma unroll
    for (int i = 0; i < 4; i++)
#pragma unroll
        for (int j = 0; j < 4; j++) acc[i][j] = 0.f;

    for (int kc = 0; kc < HID; kc += 64) {
#pragma unroll
        for (int q = 0; q < 4; q++) {
            int fi = htid + q * 256;
            int row = fi >> 4, c4 = fi & 15;
            float4 v = *(const float4*)&d_h[(size_t)(b0 + row) * HID + kc + c4 * 4];
            shh[row][c4 * 4 + 0] = v.x; shh[row][c4 * 4 + 1] = v.y;
            shh[row][c4 * 4 + 2] = v.z; shh[row][c4 * 4 + 3] = v.w;
            float4 w = *(const float4*)&hw[(size_t)row * HID + kc + c4 * 4];
            shw[row][c4 * 4 + 0] = w.x; shw[row][c4 * 4 + 1] = w.y;
            shw[row][c4 * 4 + 2] = w.z; shw[row][c4 * 4 + 3] = w.w;
        }
        __syncthreads();
#pragma unroll 4
        for (int kk = 0; kk < 64; kk++) {
            float av[4], bv[4];
#pragma unroll
            for (int i = 0; i < 4; i++) av[i] = shh[ty * 4 + i][kk];
#pragma unroll
            for (int j = 0; j < 4; j++) bv[j] = shw[tx * 4 + j][kk];
#pragma unroll
            for (int i = 0; i < 4; i++)
#pragma unroll
                for (int j = 0; j < 4; j++) acc[i][j] += av[i] * bv[j];
        }
        __syncthreads();
    }
#pragma unroll
    for (int i = 0; i < 4; i++)
#pragma unroll
        for (int j = 0; j < 4; j++)
            d_logits[(size_t)(b0 + ty * 4 + i) * ALPH + tx * 4 + j] = acc[i][j] + hb[tx * 4 + j];
}

// ---------------- the one persistent kernel ----------------
__global__ __launch_bounds__(NTHREADS, 1)
void k_all(const float* __restrict__ embed, const float* __restrict__ w_ih,
           const float* __restrict__ w_hh, const float* __restrict__ b_ih,
           const float* __restrict__ b_hh, const float* __restrict__ head_w,
           const float* __restrict__ head_b, float* __restrict__ out) {
    extern __shared__ __align__(16) char dsm[];
    const int tid = threadIdx.x;
    const int half = tid >> 8;          // two 256-thread halves for cell/head/sample
    const int htid = tid & 255;
    char* pchar_h = dsm + half * 33280; // per-half head smem (shh + shw)
    const unsigned gtid = blockIdx.x * NTHREADS + tid;
    const unsigned nth = gridDim.x * NTHREADS;
    const uint32_t dsm_u32 = smem_to_u32(dsm);

    // ---- phase 0: keys, logp zero, E precompute, W 3-limb split ----
    if (blockIdx.x == 0 && tid < SEQL) {
        uint2 y = threefry2x32(0u, 42u, 0u, (unsigned)tid);
        d_keys[2 * tid]     = y.x;
        d_keys[2 * tid + 1] = y.y;
    }
    for (unsigned i = gtid; i < BATCH; i += nth)
        out[(size_t)BATCH * SEQL + i] = 0.f;
    for (unsigned idx = gtid; idx < (ALPH + 1) * G4; idx += nth) {
        int t = idx / G4, j = idx % G4;
        const float* er = embed + t * HID;
        const float* wr = w_ih + (size_t)j * HID;
        float s = b_ih[j] + b_hh[j];
#pragma unroll 8
        for (int k = 0; k < HID; k++) s += __ldg(&er[k]) * __ldg(&wr[k]);
        d_E[idx] = s;
    }
    for (unsigned idx = gtid; idx < (unsigned)G4 * HID; idx += nth) {
        __half q0, q1, q2;
        split3(w_hh[idx], q0, q1, q2);
        d_W0[idx] = q0; d_W1[idx] = q1; d_W2[idx] = q2;
    }
    gsync();

    // ---- BOS step ----
    for (int cp2 = blockIdx.x; cp2 < BATCH / 128; cp2 += gridDim.x) {
        cell_head(cp2 * 2 + half, 0, 0, 1, pchar_h, head_w, head_b, htid);
        __syncthreads();
    }
    gsync();

    // ---- main loop ----
    for (int t = 0; t < SEQL; t++) {
        // phase A: sample(t) (independent of GEMM) then flat-pipelined GEMM
        for (int cp2 = blockIdx.x; cp2 < BATCH / 128; cp2 += gridDim.x) {
            sample_chunk(cp2 * 2 + half, t, out, htid);
        }
        if (t < SEQL - 1) {
            __syncthreads();
            gemm_phase(dsm_u32);
        }
        gsync();
        // phase B: cell+head -> logits_{t+1}
        if (t < SEQL - 1) {
            for (int cp2 = blockIdx.x; cp2 < BATCH / 128; cp2 += gridDim.x) {
                cell_head(cp2 * 2 + half, 1, 1, 0, pchar_h, head_w, head_b, htid);
                __syncthreads();
            }
        }
        gsync();
    }
}

// ---------------- launch ----------------
extern "C" void kernel_launch(void* const* d_in, const int* in_sizes, int n_in,
                              void* d_out, int out_size) {
    int off = (in_sizes[0] == (ALPH + 1) * HID) ? 0 : 1;
    const float* embed  = (const float*)d_in[off + 0];
    const float* w_ih   = (const float*)d_in[off + 1];
    const float* w_hh   = (const float*)d_in[off + 2];
    const float* b_ih   = (const float*)d_in[off + 3];
    const float* b_hh   = (const float*)d_in[off + 4];
    const float* head_w = (const float*)d_in[off + 5];
    const float* head_b = (const float*)d_in[off + 6];
    float* out = (float*)d_out;

    int dev = 0;
    cudaGetDevice(&dev);
    int nsm = 148;
    cudaDeviceGetAttribute(&nsm, cudaDevAttrMultiProcessorCount, dev);

    cudaFuncSetAttribute(k_all, cudaFuncAttributeMaxDynamicSharedMemorySize, DSM_BYTES);

    // grid must exactly match co-resident capacity for the gsync barrier
    int occ = 1;
    if (cudaOccupancyMaxActiveBlocksPerMultiprocessor(&occ, k_all, NTHREADS, DSM_BYTES)
        != cudaSuccess || occ < 1)
        occ = 1;
    if (occ > 2) occ = 2;

    k_all<<<nsm * occ, NTHREADS, DSM_BYTES>>>(embed, w_ih, w_hh, b_ih, b_hh,
                                              head_w, head_b, out);
}

// round 16
// speedup vs baseline: 1.1977x; 1.1977x over previous
#include <cuda_runtime.h>
#include <cuda_fp16.h>
#include <stdint.h>

// Problem constants
#define BATCH 16384
#define HID   512
#define ALPH  64
#define SEQL  256
#define BOSID 64
#define G4    2048            // 4*HID
#define NTILE 16              // G4/128
#define MTILE 128             // BATCH/128
#define PLANE_S 16384         // one plane-chunk: 128 rows x 128B, contiguous
#define BUFSZ (6 * PLANE_S)   // 98304
#define DSM_BYTES (2 * BUFSZ + 32)  // + mbarrier slots
#define INV2048 (1.0f/2048.0f)
#define NTHREADS 512

// ---------------- device scratch (static, allowed) ----------------
__device__ float d_h[BATCH * HID];
__device__ float d_c[BATCH * HID];
__device__ float d_gates[BATCH * G4];
__device__ float d_E[(ALPH + 1) * G4];
__device__ float d_logits[BATCH * ALPH];
__device__ int   d_tok[BATCH];
__device__ unsigned d_keys[SEQL * 2];
// 3-limb fp16 decomposition, CHUNK-MAJOR layout with in-tile XOR swizzle:
// element (row, k) of limb L lives at byte ((k>>6)*NROWS + row)*128 + (((k&63)*2) ^ ((row&7)<<4))
__device__ __align__(128) __half d_h0[BATCH * HID];
__device__ __align__(128) __half d_h1[BATCH * HID];
__device__ __align__(128) __half d_h2[BATCH * HID];
__device__ __align__(128) __half d_W0[G4 * HID];
__device__ __align__(128) __half d_W1[G4 * HID];
__device__ __align__(128) __half d_W2[G4 * HID];
__device__ unsigned g_bar = 0;
__device__ unsigned g_gen = 0;

// ---------------- helpers ----------------
__device__ __forceinline__ uint32_t smem_to_u32(const void* p) {
    uint32_t a;
    asm("{ .reg .u64 t; cvta.to.shared.u64 t, %1; cvt.u32.u64 %0, t; }" : "=r"(a) : "l"(p));
    return a;
}

#define LDSM4(r0, r1, r2, r3, addr) \
    asm volatile("ldmatrix.sync.aligned.m8n8.x4.shared.b16 {%0,%1,%2,%3}, [%4];" \
        : "=r"(r0), "=r"(r1), "=r"(r2), "=r"(r3) : "r"(addr))

#define MMA16816(d, a, b0, b1) \
    asm volatile("mma.sync.aligned.m16n8k16.row.col.f32.f16.f16.f32 " \
        "{%0,%1,%2,%3}, {%4,%5,%6,%7}, {%8,%9}, {%0,%1,%2,%3};" \
        : "+f"((d)[0]), "+f"((d)[1]), "+f"((d)[2]), "+f"((d)[3]) \
        : "r"((a)[0]), "r"((a)[1]), "r"((a)[2]), "r"((a)[3]), "r"(b0), "r"(b1))

#define BULK_G2S(sa, ga, sz, mb) \
    asm volatile("cp.async.bulk.shared::cluster.global.mbarrier::complete_tx::bytes [%0], [%1], %2, [%3];" \
        :: "r"((uint32_t)(sa)), "l"(ga), "r"((uint32_t)(sz)), "r"((uint32_t)(mb)) : "memory")

#define MBARRIER_INIT(a, n) \
    asm volatile("mbarrier.init.shared.b64 [%0], %1;" :: "r"((uint32_t)(a)), "r"((uint32_t)(n)) : "memory")
#define MBARRIER_EXPECT_TX(a, tx) \
    asm volatile("mbarrier.arrive.expect_tx.shared.b64 _, [%0], %1;" \
        :: "r"((uint32_t)(a)), "r"((uint32_t)(tx)) : "memory")
#define MBARRIER_WAIT_PARITY(a, par) do { \
    uint32_t _m = (uint32_t)(a), _p = (uint32_t)(par), _d; \
    asm volatile("{\n\t.reg .pred p;\n\t" \
        "mbarrier.try_wait.parity.acquire.cta.shared::cta.b64 p, [%1], %2;\n\t" \
        "selp.b32 %0, 1, 0, p;\n\t}" : "=r"(_d) : "r"(_m), "r"(_p) : "memory"); \
    if (!_d) { \
        asm volatile("{\n\t.reg .pred P1;\n\t" \
            "WL_%=:\n\t" \
            "mbarrier.try_wait.parity.acquire.cta.shared::cta.b64 P1, [%0], %1, 0x989680;\n\t" \
            "@P1 bra.uni WD_%=;\n\t" \
            "bra.uni WL_%=;\n\t" \
            "WD_%=:\n\t}" :: "r"(_m), "r"(_p) : "memory"); \
    } \
} while (0)
#define FENCE_PROXY_ASYNC() asm volatile("fence.proxy.async.shared::cta;" ::: "memory")

// multiply a packed half2 fragment reg by 2^-11 (exact scale)
__device__ __forceinline__ uint32_t hdescale(uint32_t v) {
    __half2 x = *reinterpret_cast<__half2*>(&v);
    x = __hmul2(x, __half2half2(__float2half(4.8828125e-4f)));
    return *reinterpret_cast<uint32_t*>(&x);
}

// exact 3-limb split: x = l0 + l1/2048 + l2/2048
__device__ __forceinline__ void split3(float x, __half& l0, __half& l1, __half& l2) {
    l0 = __float2half_rn(x);
    float r1 = x - __half2float(l0);
    l1 = __float2half_rn(r1 * 2048.f);
    float r2 = r1 - __half2float(l1) * INV2048;
    l2 = __float2half_rn(r2 * 2048.f);
}

// ---------------- grid-wide barrier (all CTAs co-resident) ----------------
__device__ __forceinline__ void gsync() {
    __threadfence();
    __syncthreads();
    if (threadIdx.x == 0) {
        unsigned nb = gridDim.x;
        unsigned gen = *(volatile unsigned*)&g_gen;
        if (atomicAdd(&g_bar, 1u) == nb - 1u) {
            atomicExch(&g_bar, 0u);
            __threadfence();
            atomicAdd(&g_gen, 1u);
        } else {
            while (*(volatile unsigned*)&g_gen == gen) __nanosleep(64);
        }
        __threadfence();
    }
    __syncthreads();
}

// ---------------- threefry2x32 (bit-exact JAX, counter mode) ----------------
__device__ __forceinline__ unsigned rotl32(unsigned v, int r) {
    return (v << r) | (v >> (32 - r));
}
__device__ __forceinline__ void tf_round(unsigned &x0, unsigned &x1, int r) {
    x0 += x1; x1 = rotl32(x1, r); x1 ^= x0;
}
__device__ __forceinline__ uint2 threefry2x32(unsigned k0, unsigned k1,
                                              unsigned x0, unsigned x1) {
    unsigned ks2 = k0 ^ k1 ^ 0x1BD11BDAu;
    x0 += k0; x1 += k1;
    tf_round(x0, x1, 13); tf_round(x0, x1, 15); tf_round(x0, x1, 26); tf_round(x0, x1, 6);
    x0 += k1; x1 += ks2 + 1u;
    tf_round(x0, x1, 17); tf_round(x0, x1, 29); tf_round(x0, x1, 16); tf_round(x0, x1, 24);
    x0 += ks2; x1 += k0 + 2u;
    tf_round(x0, x1, 13); tf_round(x0, x1, 15); tf_round(x0, x1, 26); tf_round(x0, x1, 6);
    x0 += k0; x1 += k1 + 3u;
    tf_round(x0, x1, 17); tf_round(x0, x1, 29); tf_round(x0, x1, 16); tf_round(x0, x1, 24);
    x0 += k1; x1 += ks2 + 4u;
    tf_round(x0, x1, 13); tf_round(x0, x1, 15); tf_round(x0, x1, 26); tf_round(x0, x1, 6);
    x0 += ks2; x1 += k0 + 5u;
    return make_uint2(x0, x1);
}
__device__ __forceinline__ float sigmoidf_(float x) { return 1.f / (1.f + expf(-x)); }
__device__ __forceinline__ float gumbel_from_bits(unsigned bits) {
    float u = __uint_as_float((bits >> 9) | 0x3f800000u) - 1.0f;
    u = fmaxf(1.17549435e-38f, u + 1.17549435e-38f);
    return -logf(-logf(u));
}
__device__ __forceinline__ unsigned pbits32(unsigned k0, unsigned k1, unsigned f) {
    uint2 y = threefry2x32(k0, k1, 0u, f);
    return y.x ^ y.y;
}

// ---------------- bulk prefetch: 6 x 16KB contiguous planes per chunk ------
__device__ __forceinline__ void prefetch_bulk(int c, int m0, int n0,
                                              uint32_t sbase, uint32_t mbar) {
    MBARRIER_EXPECT_TX(mbar, BUFSZ);
    BULK_G2S(sbase + 0 * PLANE_S, (const char*)d_h0 + ((size_t)c * BATCH + m0) * 128, PLANE_S, mbar);
    BULK_G2S(sbase + 1 * PLANE_S, (const char*)d_h1 + ((size_t)c * BATCH + m0) * 128, PLANE_S, mbar);
    BULK_G2S(sbase + 2 * PLANE_S, (const char*)d_h2 + ((size_t)c * BATCH + m0) * 128, PLANE_S, mbar);
    BULK_G2S(sbase + 3 * PLANE_S, (const char*)d_W0 + ((size_t)c * G4 + n0) * 128, PLANE_S, mbar);
    BULK_G2S(sbase + 4 * PLANE_S, (const char*)d_W1 + ((size_t)c * G4 + n0) * 128, PLANE_S, mbar);
    BULK_G2S(sbase + 5 * PLANE_S, (const char*)d_W2 + ((size_t)c * G4 + n0) * 128, PLANE_S, mbar);
}

// ---------------- flat-pipelined HMMA GEMM phase (bit-identical numerics) ---
__device__ void gemm_phase(uint32_t dsm_u32, int* mph) {
    const int tid = threadIdx.x;
    const int wid = tid >> 5;
    const int lane = tid & 31;
    const int mwarp = wid >> 2;      // 0..3
    const int nwarp = wid & 3;       // 0..3

    const int ntl = (MTILE * NTILE - 1 - (int)blockIdx.x) / (int)gridDim.x + 1;
    const int total = ntl * 8;
    const uint32_t mbarb = dsm_u32 + 2 * BUFSZ;   // mbar[s] at +16*s... use +8*s

    float acc1[2][4][4], acc2[2][4][4];

    const int a_r = (lane & 15);
    const int a_c2 = ((lane >> 4) << 3) * 2;
    const int b_r = ((lane >> 4) << 3) + (lane & 7);
    const int b_c2 = (((lane >> 3) & 1) << 3) * 2;
    const uint32_t a_sw = ((uint32_t)(a_r & 7)) << 4;
    const uint32_t b_sw = ((uint32_t)(b_r & 7)) << 4;

    // prologue: prefetch (tile0, chunk0)
    if (tid == 0) {
        const int t0 = blockIdx.x;
        prefetch_bulk(0, (t0 / NTILE) * 128, (t0 & (NTILE - 1)) * 128, dsm_u32, mbarb);
    }

    for (int i = 0; i < total; i++) {
        const int j = i >> 3, c = i & 7;
        const int tile = blockIdx.x + j * (int)gridDim.x;
        const int n0 = (tile & (NTILE - 1)) * 128;
        const int m0 = (tile / NTILE) * 128;

        if (c == 0) {
#pragma unroll
            for (int mi = 0; mi < 2; mi++)
#pragma unroll
                for (int ni = 0; ni < 4; ni++)
#pragma unroll
                    for (int e = 0; e < 4; e++) { acc1[mi][ni][e] = 0.f; acc2[mi][ni][e] = 0.f; }
        }

        if (i + 1 < total && tid == 0) {
            const int i2 = i + 1;
            const int j2 = i2 >> 3, c2 = i2 & 7;
            const int tl2 = blockIdx.x + j2 * (int)gridDim.x;
            prefetch_bulk(c2, (tl2 / NTILE) * 128, (tl2 & (NTILE - 1)) * 128,
                          dsm_u32 + (uint32_t)(i2 & 1) * BUFSZ, mbarb + 8 * (i2 & 1));
        }

        // wait for buffer i
        MBARRIER_WAIT_PARITY(mbarb + 8 * (i & 1), (uint32_t)(mph[i & 1] & 1));
        mph[i & 1]++;

        const uint32_t bufr = dsm_u32 + (uint32_t)(i & 1) * BUFSZ;
#pragma unroll
        for (int kk = 0; kk < 4; kk++) {
            const int kB = kk * 32;
            uint32_t a0[2][4], a1[2][4], a1d[2][4], a2[2][4];
#pragma unroll
            for (int mi = 0; mi < 2; mi++) {
                uint32_t off = (uint32_t)(mwarp * 32 + mi * 16 + a_r) * 128
                             + (((uint32_t)(kB + a_c2)) ^ a_sw);
                LDSM4(a0[mi][0], a0[mi][1], a0[mi][2], a0[mi][3], bufr + off);
                LDSM4(a1[mi][0], a1[mi][1], a1[mi][2], a1[mi][3], bufr + PLANE_S + off);
                LDSM4(a2[mi][0], a2[mi][1], a2[mi][2], a2[mi][3], bufr + 2 * PLANE_S + off);
#pragma unroll
                for (int jq = 0; jq < 4; jq++) a1d[mi][jq] = hdescale(a1[mi][jq]);
            }
#pragma unroll
            for (int grp = 0; grp < 2; grp++) {
                uint32_t off = (uint32_t)(nwarp * 32 + grp * 16 + b_r) * 128
                             + (((uint32_t)(kB + b_c2)) ^ b_sw);
                uint32_t b0[4], b1[4], b2[4];
                LDSM4(b0[0], b0[1], b0[2], b0[3], bufr + 3 * PLANE_S + off);
                LDSM4(b1[0], b1[1], b1[2], b1[3], bufr + 4 * PLANE_S + off);
                LDSM4(b2[0], b2[1], b2[2], b2[3], bufr + 5 * PLANE_S + off);
                const int ni0 = 2 * grp, ni1 = ni0 + 1;
#pragma unroll
                for (int mi = 0; mi < 2; mi++) {
                    MMA16816(acc1[mi][ni0], a0[mi], b0[0], b0[1]);   // l0*g0
                    MMA16816(acc1[mi][ni1], a0[mi], b0[2], b0[3]);
                    MMA16816(acc2[mi][ni0], a0[mi], b1[0], b1[1]);   // l0*g1
                    MMA16816(acc2[mi][ni1], a0[mi], b1[2], b1[3]);
                    MMA16816(acc2[mi][ni0], a1[mi], b0[0], b0[1]);   // l1*g0
                    MMA16816(acc2[mi][ni1], a1[mi], b0[2], b0[3]);
                    MMA16816(acc2[mi][ni0], a0[mi], b2[0], b2[1]);   // l0*g2
                    MMA16816(acc2[mi][ni1], a0[mi], b2[2], b2[3]);
                    MMA16816(acc2[mi][ni0], a2[mi], b0[0], b0[1]);   // l2*g0
                    MMA16816(acc2[mi][ni1], a2[mi], b0[2], b0[3]);
                    MMA16816(acc2[mi][ni0], a1d[mi], b1[0], b1[1]);  // (l1*2^-11)*g1
                    MMA16816(acc2[mi][ni1], a1d[mi], b1[2], b1[3]);
                }
            }
        }
        __syncthreads();   // all reads of buffer(i) done before it is re-filled

        if (c == 7) {
            const int g = lane >> 2, t4 = lane & 3;
#pragma unroll
            for (int mi = 0; mi < 2; mi++) {
                const int row = m0 + mwarp * 32 + mi * 16 + g;
#pragma unroll
                for (int ni = 0; ni < 4; ni++) {
                    const int col = n0 + nwarp * 32 + ni * 8 + 2 * t4;
                    float* Cp = d_gates + (size_t)row * G4 + col;
                    Cp[0] = acc1[mi][ni][0] + acc2[mi][ni][0] * INV2048;
                    Cp[1] = acc1[mi][ni][1] + acc2[mi][ni][1] * INV2048;
                    float* Cp2 = Cp + (size_t)8 * G4;
                    Cp2[0] = acc1[mi][ni][2] + acc2[mi][ni][2] * INV2048;
                    Cp2[1] = acc1[mi][ni][3] + acc2[mi][ni][3] * INV2048;
                }
            }
        }
    }
}

// ---------------- sample for a 64-row chunk (256-thread half) ---------------
__device__ void sample_chunk(int ch, int t, float* __restrict__ out, int htid) {
    const int b0 = ch * 64;
    const int hwid = htid >> 5;
    const int lane = htid & 31;
    const unsigned k0 = __ldcg(&d_keys[2 * t]);
    const unsigned k1 = __ldcg(&d_keys[2 * t + 1]);

    for (int rr = 0; rr < 8; rr++) {
        const int lb = hwid * 8 + rr;
        const int b = b0 + lb;

        const int a0 = lane, a1 = lane + 32;
        const unsigned f0 = (unsigned)b * ALPH + a0;
        const unsigned f1 = f0 + 32u;
        unsigned bits0 = pbits32(k0, k1, f0);
        unsigned bits1 = pbits32(k0, k1, f1);

        float l0 = d_logits[(size_t)b * ALPH + a0];
        float l1 = d_logits[(size_t)b * ALPH + a1];
        float z0 = l0 + gumbel_from_bits(bits0);
        float z1 = l1 + gumbel_from_bits(bits1);

        float v; int idx;
        if (z1 > z0) { v = z1; idx = a1; } else { v = z0; idx = a0; }
#pragma unroll
        for (int off = 16; off > 0; off >>= 1) {
            float vo = __shfl_down_sync(0xffffffffu, v, off);
            int io = __shfl_down_sync(0xffffffffu, idx, off);
            if (vo > v || (vo == v && io < idx)) { v = vo; idx = io; }
        }
        idx = __shfl_sync(0xffffffffu, idx, 0);

        float m = fmaxf(l0, l1);
#pragma unroll
        for (int off = 16; off > 0; off >>= 1)
            m = fmaxf(m, __shfl_xor_sync(0xffffffffu, m, off));
        float s = expf(l0 - m) + expf(l1 - m);
#pragma unroll
        for (int off = 16; off > 0; off >>= 1)
            s += __shfl_xor_sync(0xffffffffu, s, off);

        float ltok = __shfl_sync(0xffffffffu, (idx < 32 ? l0 : l1), idx & 31);

        if (lane == 0) {
            d_tok[b] = idx;
            out[(size_t)b * SEQL + t] = (float)idx;
            out[(size_t)BATCH * SEQL + b] += ltok - m - logf(s);
        }
    }
}

// ---------------- cell + head for a 64-row chunk (256-thread half) ----------
__device__ void cell_head(int ch, int use_tok, int has_gates, int czero,
                          char* pchar,
                          const float* __restrict__ hw, const float* __restrict__ hb,
                          int htid) {
    const int b0 = ch * 64;

    for (int e = htid; e < 64 * HID; e += 256) {
        int lr = e >> 9, k = e & (HID - 1);
        int b = b0 + lr;
        int tk = use_tok ? d_tok[b] : BOSID;
        const float* Er = d_E + (size_t)tk * G4;
        float gi = __ldcg(&Er[k]);
        float gf = __ldcg(&Er[HID + k]);
        float gg = __ldcg(&Er[2 * HID + k]);
        float go = __ldcg(&Er[3 * HID + k]);
        if (has_gates) {
            const float* g1 = d_gates + (size_t)b * G4;
            gi += __ldcg(&g1[k]);
            gf += __ldcg(&g1[HID + k]);
            gg += __ldcg(&g1[2 * HID + k]);
            go += __ldcg(&g1[3 * HID + k]);
        }
        size_t i = (size_t)b * HID + k;
        float cc = czero ? 0.f : d_c[i];
        float c2 = sigmoidf_(gf) * cc + sigmoidf_(gi) * tanhf(gg);
        d_c[i] = c2;
        float h2 = sigmoidf_(go) * tanhf(c2);
        d_h[i] = h2;
        __half q0, q1, q2;
        split3(h2, q0, q1, q2);
        // chunk-major + in-tile swizzled limb store
        uint32_t swc = ((uint32_t)((k & 63) * 2)) ^ (((uint32_t)(b & 7)) << 4);
        size_t boff = ((size_t)(k >> 6) * BATCH + b) * 128 + swc;
        *(__half*)((char*)d_h0 + boff) = q0;
        *(__half*)((char*)d_h1 + boff) = q1;
        *(__half*)((char*)d_h2 + boff) = q2;
    }
    __syncthreads();

    // head: logits[64x64] = h @ head_w^T + head_b
    float (*shh)[65] = (float (*)[65])pchar;
    float (*shw)[65] = (float (*)[65])(pchar + 64 * 65 * 4);
    const int ty = htid >> 4, tx = htid & 15;
    float acc[4][4];
#pragma unroll
    for (int i = 0; i < 4; i++)
#pragma unroll
        for (int j = 0; j < 4; j++) acc[i][j] = 0.f;

    for (int kc = 0; kc < HID; kc += 64) {
#pragma unroll
        for (int q = 0; q < 4; q++) {
            int fi = htid + q * 256;
            int row = fi >> 4, c4 = fi & 15;
            float4 v = *(const float4*)&d_h[(size_t)(b0 + row) * HID + kc + c4 * 4];
            shh[row][c4 * 4 + 0] = v.x; shh[row][c4 * 4 + 1] = v.y;
            shh[row][c4 * 4 + 2] = v.z; shh[row][c4 * 4 + 3] = v.w;
            float4 w = *(const float4*)&hw[(size_t)row * HID + kc + c4 * 4];
            shw[row][c4 * 4 + 0] = w.x; shw[row][c4 * 4 + 1] = w.y;
            shw[row][c4 * 4 + 2] = w.z; shw[row][c4 * 4 + 3] = w.w;
        }
        __syncthreads();
#pragma unroll 4
        for (int kk = 0; kk < 64; kk++) {
            float av[4], bv[4];
#pragma unroll
            for (int i = 0; i < 4; i++) av[i] = shh[ty * 4 + i][kk];
#pragma unroll
            for (int j = 0; j < 4; j++) bv[j] = shw[tx * 4 + j][kk];
#pragma unroll
            for (int i = 0; i < 4; i++)
#pragma unroll
                for (int j = 0; j < 4; j++) acc[i][j] += av[i] * bv[j];
        }
        __syncthreads();
    }
#pragma unroll
    for (int i = 0; i < 4; i++)
#pragma unroll
        for (int j = 0; j < 4; j++)
            d_logits[(size_t)(b0 + ty * 4 + i) * ALPH + tx * 4 + j] = acc[i][j] + hb[tx * 4 + j];

    // generic->async proxy ordering for the smem this head phase dirtied
    FENCE_PROXY_ASYNC();
}

// ---------------- the one persistent kernel ----------------
__global__ __launch_bounds__(NTHREADS, 1)
void k_all(const float* __restrict__ embed, const float* __restrict__ w_ih,
           const float* __restrict__ w_hh, const float* __restrict__ b_ih,
           const float* __restrict__ b_hh, const float* __restrict__ head_w,
           const float* __restrict__ head_b, float* __restrict__ out) {
    extern __shared__ __align__(16) char dsm[];
    const int tid = threadIdx.x;
    const int half = tid >> 8;
    const int htid = tid & 255;
    char* pchar_h = dsm + half * 33280;
    const unsigned gtid = blockIdx.x * NTHREADS + tid;
    const unsigned nth = gridDim.x * NTHREADS;
    const uint32_t dsm_u32 = smem_to_u32(dsm);
    int mph[2] = {0, 0};

    // mbarriers for the bulk-copy pipeline
    if (tid == 0) {
        MBARRIER_INIT(dsm_u32 + 2 * BUFSZ, 1);
        MBARRIER_INIT(dsm_u32 + 2 * BUFSZ + 8, 1);
    }

    // ---- phase 0: keys, logp zero, E precompute, W 3-limb split ----
    if (blockIdx.x == 0 && tid < SEQL) {
        uint2 y = threefry2x32(0u, 42u, 0u, (unsigned)tid);
        d_keys[2 * tid]     = y.x;
        d_keys[2 * tid + 1] = y.y;
    }
    for (unsigned i = gtid; i < BATCH; i += nth)
        out[(size_t)BATCH * SEQL + i] = 0.f;
    for (unsigned idx = gtid; idx < (ALPH + 1) * G4; idx += nth) {
        int t = idx / G4, j = idx % G4;
        const float* er = embed + t * HID;
        const float* wr = w_ih + (size_t)j * HID;
        float s = b_ih[j] + b_hh[j];
#pragma unroll 8
        for (int k = 0; k < HID; k++) s += __ldg(&er[k]) * __ldg(&wr[k]);
        d_E[idx] = s;
    }
    for (unsigned idx = gtid; idx < (unsigned)G4 * HID; idx += nth) {
        int j = idx >> 9, k = idx & (HID - 1);
        __half q0, q1, q2;
        split3(w_hh[idx], q0, q1, q2);
        uint32_t swc = ((uint32_t)((k & 63) * 2)) ^ (((uint32_t)(j & 7)) << 4);
        size_t boff = ((size_t)(k >> 6) * G4 + j) * 128 + swc;
        *(__half*)((char*)d_W0 + boff) = q0;
        *(__half*)((char*)d_W1 + boff) = q1;
        *(__half*)((char*)d_W2 + boff) = q2;
    }
    gsync();

    // ---- BOS step ----
    for (int cp2 = blockIdx.x; cp2 < BATCH / 128; cp2 += gridDim.x) {
        cell_head(cp2 * 2 + half, 0, 0, 1, pchar_h, head_w, head_b, htid);
        __syncthreads();
    }
    gsync();

    // ---- main loop ----
    for (int t = 0; t < SEQL; t++) {
        for (int cp2 = blockIdx.x; cp2 < BATCH / 128; cp2 += gridDim.x) {
            sample_chunk(cp2 * 2 + half, t, out, htid);
        }
        if (t < SEQL - 1) {
            __syncthreads();
            gemm_phase(dsm_u32, mph);
        }
        gsync();
        if (t < SEQL - 1) {
            for (int cp2 = blockIdx.x; cp2 < BATCH / 128; cp2 += gridDim.x) {
                cell_head(cp2 * 2 + half, 1, 1, 0, pchar_h, head_w, head_b, htid);
                __syncthreads();
            }
        }
        gsync();
    }
}

// ---------------- launch ----------------
extern "C" void kernel_launch(void* const* d_in, const int* in_sizes, int n_in,
                              void* d_out, int out_size) {
    int off = (in_sizes[0] == (ALPH + 1) * HID) ? 0 : 1;
    const float* embed  = (const float*)d_in[off + 0];
    const float* w_ih   = (const float*)d_in[off + 1];
    const float* w_hh   = (const float*)d_in[off + 2];
    const float* b_ih   = (const float*)d_in[off + 3];
    const float* b_hh   = (const float*)d_in[off + 4];
    const float* head_w = (const float*)d_in[off + 5];
    const float* head_b = (const float*)d_in[off + 6];
    float* out = (float*)d_out;

    int dev = 0;
    cudaGetDevice(&dev);
    int nsm = 148;
    cudaDeviceGetAttribute(&nsm, cudaDevAttrMultiProcessorCount, dev);

    cudaFuncSetAttribute(k_all, cudaFuncAttributeMaxDynamicSharedMemorySize, DSM_BYTES);

    // grid must exactly match co-resident capacity for the gsync barrier
    int occ = 1;
    if (cudaOccupancyMaxActiveBlocksPerMultiprocessor(&occ, k_all, NTHREADS, DSM_BYTES)
        != cudaSuccess || occ < 1)
        occ = 1;
    if (occ > 2) occ = 2;

    k_all<<<nsm * occ, NTHREADS, DSM_BYTES>>>(embed, w_ih, w_hh, b_ih, b_hh,
                                              head_w, head_b, out);
}